// round 8
// baseline (speedup 1.0000x reference)
#include <cuda_runtime.h>
#include <cuda_bf16.h>

// ---------------- problem constants ----------------
#define NN     200000   // nodes
#define DFEAT  128
#define EE     8192     // events
#define HH     64
#define TE     32
#define EA     32
#define AA     50
#define KMSG   (2*HH + EA + TE)   // 192
#define GRID_SCAN 148             // one block per SM -> all co-resident

// k_pre grid partition (blockDim = 256)
#define TE_BLOCKS  256            // 256*256*4 = 262144 = EE*TE
#define W2_BLOCKS  49             // 49*4 = 196 >= KMSG+1 rows
#define CNT_BLOCKS 64             // 64*256 = 16384 = 2*EE

// ---------------- scratch (static device globals; allocation is forbidden) --
// Invariant: at entry of every kernel_launch call, g_ncount == 0, g_done == 0,
// g_pred == 0 (sentinel "no predecessor" = 0; stored value is pos+1).
// Guaranteed by zero-init at module load + cleanup at the end of each call.
__device__ float g_h[(size_t)NN * HH];     // node memory (only written slots are read)
__device__ float g_c[(size_t)NN * HH];     // LSTM cell
__device__ float g_te[EE * TE];            // time encodings
__device__ float g_W2[KMSG * AA];          // fused W_emb @ W_cls
__device__ float g_b2[AA];                 // fused bias

__device__ int g_done[EE];                 // event completion flags (cleared by k_logits)
__device__ int g_ncount[NN];               // endpoint counts (cleared by k_sortpred)
__device__ int g_pred[2 * EE];             // pos+1 of predecessor endpoint (cleared by k_logits)

// ---------------- helpers ----------------
using ull = unsigned long long;

__device__ __forceinline__ ull ffma2(ull a, ull b, ull c) {
    ull d;
    asm("fma.rn.f32x2 %0, %1, %2, %3;" : "=l"(d) : "l"(a), "l"(b), "l"(c));
    return d;
}
__device__ __forceinline__ ull f2u(float x, float y) {
    ull v;
    asm("mov.b64 %0, {%1, %2};" : "=l"(v) : "f"(x), "f"(y));
    return v;
}
__device__ __forceinline__ float2 u2f(ull v) {
    float2 r;
    asm("mov.b64 {%0, %1}, %2;" : "=f"(r.x), "=f"(r.y) : "l"(v));
    return r;
}
__device__ __forceinline__ float sigm(float x) {
    return __fdividef(1.0f, 1.0f + __expf(-x));
}
__device__ __forceinline__ float tanh_s(float x) {
    float a = fabsf(x);
    float e = __expf(-2.0f * a);
    float r = __fdividef(1.0f - e, 1.0f + e);
    return copysignf(r, x);
}
__device__ __forceinline__ void wait_done(int e) {
    unsigned v;
    do {
        asm volatile("ld.global.acquire.gpu.b32 %0, [%1];" : "=r"(v) : "l"(g_done + e) : "memory");
    } while (v == 0u);
}
__device__ __forceinline__ void signal_done(int e) {
    asm volatile("st.global.release.gpu.b32 [%0], %1;" :: "l"(g_done + e), "r"(1) : "memory");
}

// ---------------- K1: fused prologue: time-enc | W2 fold | endpoint count ---
__global__ __launch_bounds__(256)
void k_pre(const float* __restrict__ etime,
           const float* __restrict__ tw,
           const float* __restrict__ tb,
           const float* __restrict__ W_emb,
           const float* __restrict__ b_emb,
           const float* __restrict__ W_cls,
           const float* __restrict__ b_cls,
           const int*   __restrict__ ei) {
    const int blk = blockIdx.x, t = threadIdx.x;
    if (blk < TE_BLOCKS) {
        // time encodings: accurate cosf (args up to ~3e4; MUFU would be wrong)
        int base = blk * 1024;
        #pragma unroll
        for (int k = 0; k < 4; k++) {
            int idx = base + k * 256 + t;
            int e = idx >> 5, i = idx & 31;
            g_te[idx] = cosf(etime[e] * tw[i] + tb[i]);
        }
    } else if (blk < TE_BLOCKS + W2_BLOCKS) {
        // W2 = W_emb @ W_cls (+ fused bias row). 4 rows per block.
        __shared__ float srow[4][HH];
        int r = (blk - TE_BLOCKS) * 4 + (t >> 6);
        int c = t & 63;
        if (r < KMSG)       srow[t >> 6][c] = W_emb[r * HH + c];
        else if (r == KMSG) srow[t >> 6][c] = b_emb[c];
        __syncthreads();
        if (r <= KMSG && c < AA) {
            float s = (r == KMSG) ? b_cls[c] : 0.0f;
            #pragma unroll 16
            for (int j = 0; j < HH; j++) s += srow[t >> 6][j] * W_cls[j * AA + c];
            if (r < KMSG) g_W2[r * AA + c] = s;
            else          g_b2[c] = s;
        }
    } else {
        // endpoint occurrence count (self-loop dst deduped)
        int i = (blk - TE_BLOCKS - W2_BLOCKS) * 256 + t;   // < 2*EE
        int e = i >> 1;
        int src = ei[e], dst = ei[EE + e];
        if (!((i & 1) && src == dst))
            atomicAdd(&g_ncount[(i & 1) ? dst : src], 1);
    }
}

// ---------------- K2: compact + bitonic sort + predecessor extraction ------
// One block, 1024 threads. Compacts multi-occurrence endpoints into smem,
// zeroes g_ncount (restoring the call-entry invariant), sorts (node,pos)
// keys, then writes g_pred[pos] = pred_pos + 1 for same-node neighbors.
// Deterministic: pos is in the sort key, so compaction order is irrelevant.
__global__ void k_sortpred(const int* __restrict__ ei) {
    extern __shared__ ull skey[];
    __shared__ int s_n;
    const int t = threadIdx.x, T = blockDim.x;
    if (t == 0) s_n = 0;
    __syncthreads();

    // compact endpoints whose node occurs >= 2 times
    for (int i = t; i < 2 * EE; i += T) {
        int e = i >> 1;
        int src = ei[e], dst = ei[EE + e];
        if ((i & 1) && src == dst) continue;       // self-loop dedup
        int v = (i & 1) ? dst : src;
        if (__ldcg(&g_ncount[v]) >= 2) {
            int pos = atomicAdd(&s_n, 1);
            skey[pos] = ((ull)(unsigned)v << 32) | (unsigned)i;
        }
    }
    __syncthreads();
    const int n = s_n;

    // restore g_ncount == 0 for every touched node (races all write 0: benign)
    for (int i = t; i < 2 * EE; i += T) {
        int e = i >> 1;
        g_ncount[(i & 1) ? ei[EE + e] : ei[e]] = 0;
    }

    int m = 2;
    while (m < n) m <<= 1;                          // n <= 16384
    for (int i = t; i < m; i += T) if (i >= n) skey[i] = ~0ull;
    __syncthreads();

    for (int k = 2; k <= m; k <<= 1) {
        for (int j = k >> 1; j > 0; j >>= 1) {
            for (int i = t; i < m; i += T) {
                int ixj = i ^ j;
                if (ixj > i) {
                    ull a = skey[i], b = skey[ixj];
                    bool up = ((i & k) == 0);
                    if ((a > b) == up) { skey[i] = b; skey[ixj] = a; }
                }
            }
            __syncthreads();
        }
    }
    for (int i = t + 1; i < n; i += T) {
        ull a = skey[i - 1], b = skey[i];
        if ((a >> 32) == (b >> 32))
            g_pred[(unsigned)b] = (int)(unsigned)a + 1;   // pos+1 (0 = none)
    }
}

// ---------------- K3: parallel dependency-driven event scan ----------------
// 148 persistent blocks (all co-resident). Block b owns events b, b+148, ...
// Exact sequential semantics via per-endpoint predecessor flags.
// Zero-state invariant: pred == 0 => that node's (h,c) is exactly 0.
__global__ __launch_bounds__(256, 1)
void k_scan(const int*   __restrict__ ei,
            const float* __restrict__ eattr,
            const float* __restrict__ W_msg,
            const float* __restrict__ b_msg,
            const float* __restrict__ W_ih,
            const float* __restrict__ W_hh,
            const float* __restrict__ b_lstm) {
    __shared__ __align__(16) float s_f0[KMSG];   // feat row0: [hd|hs|ea|te]
    __shared__ __align__(16) float s_f1[KMSG];   // feat row1: [hs|hd|ea|te]
    __shared__ __align__(16) float s_m0[HH];     // relu message row0
    __shared__ __align__(16) float s_m1[HH];     // relu message row1
    __shared__ __align__(16) float s_c[2][HH];   // old cell (cs, cd)
    __shared__ float2 s_part[4][HH];             // message partials {r0, r1}
    __shared__ float2 s_g[4 * HH];               // gates {r0, r1}
    __shared__ float  s_bmsg[HH];
    __shared__ float  s_blstm[4 * HH];

    const int t   = threadIdx.x;
    const int col = t & 63;
    const int seg = t >> 6;
    const int k0  = seg * 48;

    if (t < HH) s_bmsg[t] = b_msg[t];
    s_blstm[t] = b_lstm[t];

    // message weights: this thread holds W_msg[k0..k0+48)[col], k-paired
    ull wm[24];
    #pragma unroll
    for (int j = 0; j < 24; j++)
        wm[j] = f2u(W_msg[(k0 + 2*j) * HH + col], W_msg[(k0 + 2*j + 1) * HH + col]);

    // LSTM weights: full columns t of W_ih and W_hh, k-paired
    ull wih[32], whh[32];
    #pragma unroll
    for (int i = 0; i < 32; i++) {
        wih[i] = f2u(W_ih[(2*i) * 256 + t], W_ih[(2*i + 1) * 256 + t]);
        whh[i] = f2u(W_hh[(2*i) * 256 + t], W_hh[(2*i + 1) * 256 + t]);
    }
    __syncthreads();

    for (int e = blockIdx.x; e < EE; e += GRID_SCAN) {
        const int src = ei[e];
        const int dst = ei[EE + e];
        const int ps  = g_pred[2 * e];
        int       pd  = g_pred[2 * e + 1];
        if (src == dst) pd = ps;   // self-loop: dst endpoint was deduped

        // ---- per-thread wait + state load (zeros when no predecessor) ----
        if (t < 64) {
            float vh = 0.0f, vc = 0.0f;
            if (pd > 0) {
                wait_done((pd - 1) >> 1);
                vh = __ldcg(&g_h[(size_t)dst * HH + t]);
                vc = __ldcg(&g_c[(size_t)dst * HH + t]);
            }
            s_f0[t] = vh;           // row0 leading = hd
            s_f1[64 + t] = vh;      // row1 second  = hd
            s_c[1][t] = vc;
        } else if (t < 128) {
            int i = t - 64;
            float vh = 0.0f, vc = 0.0f;
            if (ps > 0) {
                wait_done((ps - 1) >> 1);
                vh = __ldcg(&g_h[(size_t)src * HH + i]);
                vc = __ldcg(&g_c[(size_t)src * HH + i]);
            }
            s_f0[64 + i] = vh;      // row0 second  = hs
            s_f1[i] = vh;           // row1 leading = hs
            s_c[0][i] = vc;
        } else if (t < 160) {
            int i = t - 128;
            float v = eattr[e * EA + i];
            s_f0[128 + i] = v;
            s_f1[128 + i] = v;
        } else if (t < 192) {
            int i = t - 160;
            float v = g_te[e * TE + i];
            s_f0[160 + i] = v;
            s_f1[160 + i] = v;
        }
        __syncthreads();

        // ---- message GEMM: [2,192] @ [192,64] (LDS.128, 4 accumulators) ----
        {
            ull a0 = 0ull, a1 = 0ull, c0 = 0ull, c1 = 0ull;
            #pragma unroll
            for (int j = 0; j < 12; j++) {
                ulonglong2 F0 = *(const ulonglong2*)(s_f0 + k0 + 4*j);
                ulonglong2 F1 = *(const ulonglong2*)(s_f1 + k0 + 4*j);
                a0 = ffma2(F0.x, wm[2*j],     a0);
                c0 = ffma2(F0.y, wm[2*j + 1], c0);
                a1 = ffma2(F1.x, wm[2*j],     a1);
                c1 = ffma2(F1.y, wm[2*j + 1], c1);
            }
            float2 p0 = u2f(a0), q0 = u2f(c0), p1 = u2f(a1), q1 = u2f(c1);
            s_part[seg][col] = make_float2(p0.x + p0.y + q0.x + q0.y,
                                           p1.x + p1.y + q1.x + q1.y);
        }
        __syncthreads();

        if (t < HH) {
            float2 s = s_part[0][t];
            #pragma unroll
            for (int q = 1; q < 4; q++) { s.x += s_part[q][t].x; s.y += s_part[q][t].y; }
            float b = s_bmsg[t];
            s_m0[t] = fmaxf(s.x + b, 0.0f);
            s_m1[t] = fmaxf(s.y + b, 0.0f);
        }
        __syncthreads();

        // ---- LSTM gates: g = m@W_ih + h_old@W_hh + b (LDS.128, split acc) --
        {
            ull a0 = 0ull, b0 = 0ull, a1 = 0ull, b1 = 0ull;
            #pragma unroll
            for (int i = 0; i < 16; i++) {
                ulonglong2 M0 = *(const ulonglong2*)(s_m0 + 4*i);
                ulonglong2 M1 = *(const ulonglong2*)(s_m1 + 4*i);
                ulonglong2 F0 = *(const ulonglong2*)(s_f0 + 64 + 4*i);
                ulonglong2 F1 = *(const ulonglong2*)(s_f1 + 64 + 4*i);
                a0 = ffma2(M0.x, wih[2*i], a0);  a0 = ffma2(M0.y, wih[2*i + 1], a0);
                a1 = ffma2(M1.x, wih[2*i], a1);  a1 = ffma2(M1.y, wih[2*i + 1], a1);
                b0 = ffma2(F0.x, whh[2*i], b0);  b0 = ffma2(F0.y, whh[2*i + 1], b0);
                b1 = ffma2(F1.x, whh[2*i], b1);  b1 = ffma2(F1.y, whh[2*i + 1], b1);
            }
            float2 g0 = u2f(a0), h0 = u2f(b0), g1 = u2f(a1), h1 = u2f(b1);
            float b = s_blstm[t];
            s_g[t] = make_float2(g0.x + g0.y + h0.x + h0.y + b,
                                 g1.x + g1.y + h1.x + h1.y + b);
        }
        __syncthreads();

        // ---- elementwise LSTM + writeback ----
        if (t < 128) {
            int r = t >> 6, cc = t & 63;
            float2 vi = s_g[cc], vf = s_g[64 + cc], vg = s_g[128 + cc], vo = s_g[192 + cc];
            float gi = r ? vi.y : vi.x;
            float gf = r ? vf.y : vf.x;
            float gg = r ? vg.y : vg.x;
            float go = r ? vo.y : vo.x;
            float co = s_c[r][cc];
            float cn = sigm(gf) * co + sigm(gi) * tanh_s(gg);
            float hn = sigm(go) * tanh_s(cn);
            int node = r ? dst : src;
            // duplicate-index semantics: dst (row 1) wins, matching scatter order
            if (!(r == 0 && src == dst)) {
                __stcg(&g_h[(size_t)node * HH + cc], hn);
                __stcg(&g_c[(size_t)node * HH + cc], cn);
            }
        }
        __syncthreads();                 // writes done block-wide before release

        if (t == 0) signal_done(e);      // release: publishes h/c to consumers
    }
}

// ---------------- K4: logits + scratch cleanup -----------------------------
__global__ void k_logits(const int* __restrict__ ei,
                         const float* __restrict__ x,
                         float* __restrict__ out) {
    __shared__ float sz[KMSG];
    int e = blockIdx.x;
    int dst = ei[EE + e];
    int t = threadIdx.x;   // 64 threads
    if (t == 0) {          // restore call-entry invariant for next replay
        g_done[e] = 0;
        g_pred[2 * e] = 0;
        g_pred[2 * e + 1] = 0;
    }
    sz[t]       = g_h[(size_t)dst * HH + t];   // written by scan (dst of event e)
    sz[64 + t]  = x[(size_t)dst * DFEAT + t];
    sz[128 + t] = x[(size_t)dst * DFEAT + 64 + t];
    __syncthreads();
    if (t < AA) {
        float s = g_b2[t];
        #pragma unroll 8
        for (int i = 0; i < KMSG; i++) s += sz[i] * g_W2[i * AA + t];
        out[e * AA + t] = s;
    }
}

// ---------------- launch ----------------
extern "C" void kernel_launch(void* const* d_in, const int* in_sizes, int n_in,
                              void* d_out, int out_size) {
    const float* x      = (const float*)d_in[0];
    const int*   ei     = (const int*)  d_in[1];
    const float* eattr  = (const float*)d_in[2];
    const float* etime  = (const float*)d_in[3];
    const float* tw     = (const float*)d_in[4];
    const float* tb     = (const float*)d_in[5];
    const float* Wmsg   = (const float*)d_in[6];
    const float* bmsg   = (const float*)d_in[7];
    const float* Wih    = (const float*)d_in[8];
    const float* Whh    = (const float*)d_in[9];
    const float* blstm  = (const float*)d_in[10];
    const float* Wemb   = (const float*)d_in[11];
    const float* bemb   = (const float*)d_in[12];
    const float* Wcls   = (const float*)d_in[13];
    const float* bcls   = (const float*)d_in[14];
    float* out = (float*)d_out;

    // idempotent host-side call (not a stream op) -> capture-safe
    cudaFuncSetAttribute(k_sortpred,
                         cudaFuncAttributeMaxDynamicSharedMemorySize,
                         2 * EE * (int)sizeof(unsigned long long));

    k_pre     <<<TE_BLOCKS + W2_BLOCKS + CNT_BLOCKS, 256>>>(
                  etime, tw, tb, Wemb, bemb, Wcls, bcls, ei);
    k_sortpred<<<1, 1024, 2 * EE * (int)sizeof(unsigned long long)>>>(ei);
    k_scan    <<<GRID_SCAN, 256>>>(ei, eattr, Wmsg, bmsg, Wih, Whh, blstm);
    k_logits  <<<EE, HH>>>(ei, x, out);
}

// round 9
// speedup vs baseline: 1.0649x; 1.0649x over previous
#include <cuda_runtime.h>
#include <cuda_bf16.h>

// ---------------- problem constants ----------------
#define NN     200000   // nodes
#define DFEAT  128
#define EE     8192     // events
#define HH     64
#define TE     32
#define EA     32
#define AA     50
#define KMSG   (2*HH + EA + TE)   // 192
#define GRID_SCAN 148             // one block per SM -> all co-resident

// ---------------- scratch (static device globals; allocation is forbidden) --
__device__ float g_h[(size_t)NN * HH];     // node memory (only written slots are ever read)
__device__ float g_c[(size_t)NN * HH];     // LSTM cell
__device__ float g_te[EE * TE];            // time encodings
__device__ float g_W2[KMSG * AA];          // fused W_emb @ W_cls
__device__ float g_b2[AA];                 // fused bias

__device__ int                g_done[EE];      // event completion flags
__device__ int                g_ncount[NN];    // endpoint occurrence counts
__device__ int                g_pred[2 * EE];  // per-endpoint predecessor position (-1 = none)
__device__ unsigned long long g_list[2 * EE];  // (node<<32)|pos for multi-occurrence endpoints
__device__ int                g_npos;          // compacted count

// ---------------- helpers ----------------
using ull = unsigned long long;

__device__ __forceinline__ ull ffma2(ull a, ull b, ull c) {
    ull d;
    asm("fma.rn.f32x2 %0, %1, %2, %3;" : "=l"(d) : "l"(a), "l"(b), "l"(c));
    return d;
}
__device__ __forceinline__ ull f2u(float x, float y) {
    ull v;
    asm("mov.b64 %0, {%1, %2};" : "=l"(v) : "f"(x), "f"(y));
    return v;
}
__device__ __forceinline__ float2 u2f(ull v) {
    float2 r;
    asm("mov.b64 {%0, %1}, %2;" : "=f"(r.x), "=f"(r.y) : "l"(v));
    return r;
}
__device__ __forceinline__ float sigm(float x) {
    return __fdividef(1.0f, 1.0f + __expf(-x));
}
__device__ __forceinline__ float tanh_s(float x) {
    float a = fabsf(x);
    float e = __expf(-2.0f * a);
    float r = __fdividef(1.0f - e, 1.0f + e);
    return copysignf(r, x);
}
__device__ __forceinline__ void wait_done(int e) {
    unsigned v;
    do {
        asm volatile("ld.global.acquire.gpu.b32 %0, [%1];" : "=r"(v) : "l"(g_done + e) : "memory");
    } while (v == 0u);
}
__device__ __forceinline__ void signal_done(int e) {
    asm volatile("st.global.release.gpu.b32 [%0], %1;" :: "l"(g_done + e), "r"(1) : "memory");
}

// ---------------- K0: reset scratch ----------------
__global__ void k_reset() {
    int i = blockIdx.x * blockDim.x + threadIdx.x;
    if (i < NN) g_ncount[i] = 0;
    if (i < EE) g_done[i] = 0;
    if (i < 2 * EE) g_pred[i] = -1;
    if (i == 0) g_npos = 0;
}

// ---------------- K1a: time encodings (accurate cosf) ----------------------
__global__ void k_te(const float* __restrict__ etime,
                     const float* __restrict__ tw,
                     const float* __restrict__ tb) {
    int idx = blockIdx.x * blockDim.x + threadIdx.x;
    if (idx < EE * TE) {
        int e = idx >> 5, i = idx & 31;
        g_te[idx] = cosf(etime[e] * tw[i] + tb[i]);
    }
}

// ---------------- K1b: fold output linears: W2 = W_emb@W_cls --------------
__global__ void k_w2(const float* __restrict__ W_emb,
                     const float* __restrict__ b_emb,
                     const float* __restrict__ W_cls,
                     const float* __restrict__ b_cls) {
    __shared__ float srow[HH];
    const int blk = blockIdx.x, t = threadIdx.x;
    if (blk < KMSG) {
        srow[t] = W_emb[blk * HH + t];
        __syncthreads();
        if (t < AA) {
            float s = 0.0f;
            #pragma unroll 16
            for (int j = 0; j < HH; j++) s += srow[j] * W_cls[j * AA + t];
            g_W2[blk * AA + t] = s;
        }
    } else {
        srow[t] = b_emb[t];
        __syncthreads();
        if (t < AA) {
            float s = b_cls[t];
            #pragma unroll 16
            for (int j = 0; j < HH; j++) s += srow[j] * W_cls[j * AA + t];
            g_b2[t] = s;
        }
    }
}

// ---------------- P1: count endpoint occurrences (self-loops deduped) ------
__global__ void k_count(const int* __restrict__ ei) {
    int i = blockIdx.x * blockDim.x + threadIdx.x;
    if (i >= 2 * EE) return;
    int e = i >> 1;
    int src = ei[e], dst = ei[EE + e];
    if ((i & 1) && src == dst) return;           // dedupe self-loop endpoint
    atomicAdd(&g_ncount[(i & 1) ? dst : src], 1);
}

// ---------------- P2: compact multi-occurrence endpoints -------------------
__global__ void k_compact(const int* __restrict__ ei) {
    int i = blockIdx.x * blockDim.x + threadIdx.x;
    if (i >= 2 * EE) return;
    int e = i >> 1;
    int src = ei[e], dst = ei[EE + e];
    if ((i & 1) && src == dst) return;
    int v = (i & 1) ? dst : src;
    if (g_ncount[v] >= 2) {
        int pos = atomicAdd(&g_npos, 1);
        g_list[pos] = ((ull)(unsigned)v << 32) | (unsigned)i;
    }
}

// ---------------- P3: bitonic sort -> predecessor extraction ---------------
// One block. Sort (node,pos) keys ascending; equal-node neighbors give pred.
// Deterministic regardless of P2's atomic compaction order (pos is in the key).
__global__ void k_sort_pred() {
    extern __shared__ ull skey[];
    const int t = threadIdx.x, T = blockDim.x;
    const int n = g_npos;
    int m = 2;
    while (m < n) m <<= 1;                       // n <= 16384

    for (int i = t; i < m; i += T)
        skey[i] = (i < n) ? g_list[i] : ~0ull;
    __syncthreads();

    for (int k = 2; k <= m; k <<= 1) {
        for (int j = k >> 1; j > 0; j >>= 1) {
            for (int i = t; i < m; i += T) {
                int ixj = i ^ j;
                if (ixj > i) {
                    ull a = skey[i], b = skey[ixj];
                    bool up = ((i & k) == 0);
                    if ((a > b) == up) { skey[i] = b; skey[ixj] = a; }
                }
            }
            __syncthreads();
        }
    }
    for (int i = t + 1; i < n; i += T) {
        ull a = skey[i - 1], b = skey[i];
        if ((a >> 32) == (b >> 32))
            g_pred[(unsigned)b] = (int)(unsigned)a;   // low 32 bits = position
    }
}

// ---------------- K2: parallel dependency-driven event scan ----------------
// 148 persistent blocks. Block b owns events b, b+148, ...  Exact sequential
// semantics via per-endpoint predecessor flags. Zero-state invariant:
// pred == -1  =>  that node's (h,c) is exactly 0, so no global load needed.
__global__ __launch_bounds__(256, 1)
void k_scan(const int*   __restrict__ ei,
            const float* __restrict__ eattr,
            const float* __restrict__ W_msg,
            const float* __restrict__ b_msg,
            const float* __restrict__ W_ih,
            const float* __restrict__ W_hh,
            const float* __restrict__ b_lstm) {
    __shared__ __align__(16) float s_f0[KMSG];   // feat row0: [hd|hs|ea|te]
    __shared__ __align__(16) float s_f1[KMSG];   // feat row1: [hs|hd|ea|te]
    __shared__ __align__(16) float s_m0[HH];     // relu message row0
    __shared__ __align__(16) float s_m1[HH];     // relu message row1
    __shared__ __align__(16) float s_c[2][HH];   // old cell (cs, cd)
    __shared__ float2 s_part[4][HH];             // message partials {r0, r1}
    __shared__ float2 s_g[4 * HH];               // gates {r0, r1}
    __shared__ float  s_bmsg[HH];
    __shared__ float  s_blstm[4 * HH];

    const int t   = threadIdx.x;
    const int col = t & 63;
    const int seg = t >> 6;
    const int k0  = seg * 48;

    if (t < HH) s_bmsg[t] = b_msg[t];
    s_blstm[t] = b_lstm[t];

    // message weights: this thread holds W_msg[k0..k0+48)[col], k-paired
    ull wm[24];
    #pragma unroll
    for (int j = 0; j < 24; j++)
        wm[j] = f2u(W_msg[(k0 + 2*j) * HH + col], W_msg[(k0 + 2*j + 1) * HH + col]);

    // LSTM weights: full columns t of W_ih and W_hh, k-paired
    ull wih[32], whh[32];
    #pragma unroll
    for (int i = 0; i < 32; i++) {
        wih[i] = f2u(W_ih[(2*i) * 256 + t], W_ih[(2*i + 1) * 256 + t]);
        whh[i] = f2u(W_hh[(2*i) * 256 + t], W_hh[(2*i + 1) * 256 + t]);
    }
    __syncthreads();

    for (int e = blockIdx.x; e < EE; e += GRID_SCAN) {
        const int src = ei[e];
        const int dst = ei[EE + e];
        const int ps  = g_pred[2 * e];
        int       pd  = g_pred[2 * e + 1];
        if (src == dst) pd = ps;   // self-loop: dst endpoint was deduped

        // ---- per-thread wait + state load (zeros when no predecessor) ----
        if (t < 64) {
            float vh = 0.0f, vc = 0.0f;
            if (pd >= 0) {
                wait_done(pd >> 1);
                vh = __ldcg(&g_h[(size_t)dst * HH + t]);
                vc = __ldcg(&g_c[(size_t)dst * HH + t]);
            }
            s_f0[t] = vh;           // row0 leading = hd
            s_f1[64 + t] = vh;      // row1 second  = hd
            s_c[1][t] = vc;
        } else if (t < 128) {
            int i = t - 64;
            float vh = 0.0f, vc = 0.0f;
            if (ps >= 0) {
                wait_done(ps >> 1);
                vh = __ldcg(&g_h[(size_t)src * HH + i]);
                vc = __ldcg(&g_c[(size_t)src * HH + i]);
            }
            s_f0[64 + i] = vh;      // row0 second  = hs
            s_f1[i] = vh;           // row1 leading = hs
            s_c[0][i] = vc;
        } else if (t < 160) {
            int i = t - 128;
            float v = eattr[e * EA + i];
            s_f0[128 + i] = v;
            s_f1[128 + i] = v;
        } else if (t < 192) {
            int i = t - 160;
            float v = g_te[e * TE + i];
            s_f0[160 + i] = v;
            s_f1[160 + i] = v;
        }
        __syncthreads();

        // ---- message GEMM: [2,192] @ [192,64] (4 k-segment partials) ----
        {
            ull a0 = 0ull, a1 = 0ull;
            #pragma unroll
            for (int j = 0; j < 24; j++) {
                ull f0 = *(const ull*)(s_f0 + k0 + 2*j);
                ull f1 = *(const ull*)(s_f1 + k0 + 2*j);
                a0 = ffma2(f0, wm[j], a0);
                a1 = ffma2(f1, wm[j], a1);
            }
            float2 p0 = u2f(a0), p1 = u2f(a1);
            s_part[seg][col] = make_float2(p0.x + p0.y, p1.x + p1.y);
        }
        __syncthreads();

        if (t < HH) {
            float2 s = s_part[0][t];
            #pragma unroll
            for (int q = 1; q < 4; q++) { s.x += s_part[q][t].x; s.y += s_part[q][t].y; }
            float b = s_bmsg[t];
            s_m0[t] = fmaxf(s.x + b, 0.0f);
            s_m1[t] = fmaxf(s.y + b, 0.0f);
        }
        __syncthreads();

        // ---- LSTM gates: g = m@W_ih + h_old@W_hh + b (split accumulators) --
        {
            ull a0 = 0ull, b0 = 0ull, a1 = 0ull, b1 = 0ull;
            #pragma unroll
            for (int i = 0; i < 32; i++) {
                a0 = ffma2(*(const ull*)(s_m0 + 2*i),      wih[i], a0);
                a1 = ffma2(*(const ull*)(s_m1 + 2*i),      wih[i], a1);
                b0 = ffma2(*(const ull*)(s_f0 + 64 + 2*i), whh[i], b0);  // hs (row0)
                b1 = ffma2(*(const ull*)(s_f1 + 64 + 2*i), whh[i], b1);  // hd (row1)
            }
            float2 g0 = u2f(a0), h0 = u2f(b0), g1 = u2f(a1), h1 = u2f(b1);
            float b = s_blstm[t];
            s_g[t] = make_float2(g0.x + g0.y + h0.x + h0.y + b,
                                 g1.x + g1.y + h1.x + h1.y + b);
        }
        __syncthreads();

        // ---- elementwise LSTM + writeback ----
        if (t < 128) {
            int r = t >> 6, cc = t & 63;
            float2 vi = s_g[cc], vf = s_g[64 + cc], vg = s_g[128 + cc], vo = s_g[192 + cc];
            float gi = r ? vi.y : vi.x;
            float gf = r ? vf.y : vf.x;
            float gg = r ? vg.y : vg.x;
            float go = r ? vo.y : vo.x;
            float co = s_c[r][cc];
            float cn = sigm(gf) * co + sigm(gi) * tanh_s(gg);
            float hn = sigm(go) * tanh_s(cn);
            int node = r ? dst : src;
            // duplicate-index semantics: dst (row 1) wins, matching scatter order
            if (!(r == 0 && src == dst)) {
                __stcg(&g_h[(size_t)node * HH + cc], hn);
                __stcg(&g_c[(size_t)node * HH + cc], cn);
            }
        }
        __syncthreads();                 // writes done block-wide before release

        if (t == 0) signal_done(e);      // release: publishes h/c to consumers
    }
}

// ---------------- K3: logits[e] = [h[dst] || x[dst]] @ W2 + b2 -------------
// 256 blocks x 256 threads. W2 (192x50) + b2 staged in smem once per block;
// each warp handles 4 edges: gathers z = [h[dst] || x[dst]] into a per-warp
// smem buffer, then two column passes (cols 0-31, 32-49) with broadcast
// float4 z reads and conflict-free sW2 reads (consecutive lanes -> consecutive
// addresses).
#define LOG_BLOCKS 256
__global__ __launch_bounds__(256)
void k_logits(const int* __restrict__ ei,
              const float* __restrict__ x,
              float* __restrict__ out) {
    __shared__ __align__(16) float sW2[KMSG * AA];  // 38.4 KB
    __shared__ float sb2[AA];
    __shared__ __align__(16) float zbuf[8][KMSG];   // per-warp z staging

    const int t    = threadIdx.x;
    const int warp = t >> 5;
    const int lane = t & 31;

    for (int i = t; i < KMSG * AA; i += 256) sW2[i] = g_W2[i];
    if (t < AA) sb2[t] = g_b2[t];
    __syncthreads();

    #pragma unroll
    for (int it = 0; it < 4; it++) {
        int e = blockIdx.x * 8 + warp + it * (LOG_BLOCKS * 8);
        int dst = ei[EE + e];

        // gather z: h[dst] (64) then x[dst] (128); 6 floats per lane
        {
            const float* hp = &g_h[(size_t)dst * HH];
            const float* xp = &x[(size_t)dst * DFEAT];
            zbuf[warp][lane]       = hp[lane];
            zbuf[warp][lane + 32]  = hp[lane + 32];
            zbuf[warp][lane + 64]  = xp[lane];
            zbuf[warp][lane + 96]  = xp[lane + 32];
            zbuf[warp][lane + 128] = xp[lane + 64];
            zbuf[warp][lane + 160] = xp[lane + 96];
        }
        __syncwarp();

        // pass 0: cols 0..31   pass 1: cols 32..49
        #pragma unroll
        for (int p = 0; p < 2; p++) {
            int c = p * 32 + lane;
            if (c < AA) {
                float acc = sb2[c];
                #pragma unroll 8
                for (int i = 0; i < KMSG; i += 4) {
                    float4 z4 = *(const float4*)(&zbuf[warp][i]);   // broadcast
                    acc += z4.x * sW2[(i    ) * AA + c];
                    acc += z4.y * sW2[(i + 1) * AA + c];
                    acc += z4.z * sW2[(i + 2) * AA + c];
                    acc += z4.w * sW2[(i + 3) * AA + c];
                }
                out[e * AA + c] = acc;
            }
        }
        __syncwarp();
    }
}

// ---------------- launch ----------------
extern "C" void kernel_launch(void* const* d_in, const int* in_sizes, int n_in,
                              void* d_out, int out_size) {
    const float* x      = (const float*)d_in[0];
    const int*   ei     = (const int*)  d_in[1];
    const float* eattr  = (const float*)d_in[2];
    const float* etime  = (const float*)d_in[3];
    const float* tw     = (const float*)d_in[4];
    const float* tb     = (const float*)d_in[5];
    const float* Wmsg   = (const float*)d_in[6];
    const float* bmsg   = (const float*)d_in[7];
    const float* Wih    = (const float*)d_in[8];
    const float* Whh    = (const float*)d_in[9];
    const float* blstm  = (const float*)d_in[10];
    const float* Wemb   = (const float*)d_in[11];
    const float* bemb   = (const float*)d_in[12];
    const float* Wcls   = (const float*)d_in[13];
    const float* bcls   = (const float*)d_in[14];
    float* out = (float*)d_out;

    // idempotent, host-side only (not a stream op) -> safe under capture
    cudaFuncSetAttribute(k_sort_pred,
                         cudaFuncAttributeMaxDynamicSharedMemorySize,
                         2 * EE * (int)sizeof(unsigned long long));

    k_reset  <<<(NN + 255) / 256, 256>>>();
    k_te     <<<(EE * TE + 255) / 256, 256>>>(etime, tw, tb);
    k_w2     <<<KMSG + 1, HH>>>(Wemb, bemb, Wcls, bcls);
    k_count  <<<(2 * EE + 255) / 256, 256>>>(ei);
    k_compact<<<(2 * EE + 255) / 256, 256>>>(ei);
    k_sort_pred<<<1, 1024, 2 * EE * (int)sizeof(unsigned long long)>>>();
    k_scan   <<<GRID_SCAN, 256>>>(ei, eattr, Wmsg, bmsg, Wih, Whh, blstm);
    k_logits <<<LOG_BLOCKS, 256>>>(ei, x, out);
}

// round 11
// speedup vs baseline: 1.1148x; 1.0469x over previous
#include <cuda_runtime.h>
#include <cuda_bf16.h>

// ---------------- problem constants ----------------
#define NN     200000   // nodes
#define DFEAT  128
#define EE     8192     // events
#define HH     64
#define TE     32
#define EA     32
#define AA     50
#define KMSG   (2*HH + EA + TE)   // 192
#define GRID_SCAN 148             // one block per SM -> all co-resident

// k_pre grid partition (blockDim = 256)
#define TE_BLOCKS  256            // 256*1024 = 262144 = EE*TE
#define W2_BLOCKS  49             // 49*4 = 196 >= KMSG+1 rows
#define CNT_BLOCKS 64             // 64*256 = 16384 = 2*EE

// ---------------- scratch (static device globals; allocation is forbidden) --
// Call-entry invariant: g_ncount == 0, g_done == 0, g_pred == 0, g_npos == 0.
// Holds at module load (zero-init) and is restored by k_logits each call.
__device__ float g_h[(size_t)NN * HH];     // node memory (only written slots are read)
__device__ float g_c[(size_t)NN * HH];     // LSTM cell
__device__ float g_te[EE * TE];            // time encodings
__device__ float g_W2[KMSG * AA];          // fused W_emb @ W_cls
__device__ float g_b2[AA];                 // fused bias

__device__ int                g_done[EE];      // event completion flags
__device__ int                g_ncount[NN];    // endpoint occurrence counts
__device__ int                g_pred[2 * EE];  // pos+1 of predecessor endpoint (0 = none)
__device__ unsigned long long g_list[2 * EE];  // (node<<32)|pos for multi-occurrence endpoints
__device__ int                g_npos;          // compacted count

// ---------------- helpers ----------------
using ull = unsigned long long;

__device__ __forceinline__ ull ffma2(ull a, ull b, ull c) {
    ull d;
    asm("fma.rn.f32x2 %0, %1, %2, %3;" : "=l"(d) : "l"(a), "l"(b), "l"(c));
    return d;
}
__device__ __forceinline__ ull f2u(float x, float y) {
    ull v;
    asm("mov.b64 %0, {%1, %2};" : "=l"(v) : "f"(x), "f"(y));
    return v;
}
__device__ __forceinline__ float2 u2f(ull v) {
    float2 r;
    asm("mov.b64 {%0, %1}, %2;" : "=f"(r.x), "=f"(r.y) : "l"(v));
    return r;
}
__device__ __forceinline__ float sigm(float x) {
    return __fdividef(1.0f, 1.0f + __expf(-x));
}
__device__ __forceinline__ float tanh_s(float x) {
    float a = fabsf(x);
    float e = __expf(-2.0f * a);
    float r = __fdividef(1.0f - e, 1.0f + e);
    return copysignf(r, x);
}
__device__ __forceinline__ void wait_done(int e) {
    unsigned v;
    do {
        asm volatile("ld.global.acquire.gpu.b32 %0, [%1];" : "=r"(v) : "l"(g_done + e) : "memory");
    } while (v == 0u);
}
__device__ __forceinline__ void signal_done(int e) {
    asm volatile("st.global.release.gpu.b32 [%0], %1;" :: "l"(g_done + e), "r"(1) : "memory");
}

// ---------------- K1: fused prologue: time-enc | W2 fold | endpoint count ---
__global__ __launch_bounds__(256)
void k_pre(const float* __restrict__ etime,
           const float* __restrict__ tw,
           const float* __restrict__ tb,
           const float* __restrict__ W_emb,
           const float* __restrict__ b_emb,
           const float* __restrict__ W_cls,
           const float* __restrict__ b_cls,
           const int*   __restrict__ ei) {
    const int blk = blockIdx.x, t = threadIdx.x;
    if (blk < TE_BLOCKS) {
        // time encodings: accurate cosf (args up to ~3e4; MUFU would be wrong)
        int base = blk * 1024;
        #pragma unroll
        for (int k = 0; k < 4; k++) {
            int idx = base + k * 256 + t;
            int e = idx >> 5, i = idx & 31;
            g_te[idx] = cosf(etime[e] * tw[i] + tb[i]);
        }
    } else if (blk < TE_BLOCKS + W2_BLOCKS) {
        // W2 = W_emb @ W_cls (+ fused bias row). 4 rows per block.
        __shared__ float srow[4][HH];
        int r = (blk - TE_BLOCKS) * 4 + (t >> 6);
        int c = t & 63;
        if (r < KMSG)       srow[t >> 6][c] = W_emb[r * HH + c];
        else if (r == KMSG) srow[t >> 6][c] = b_emb[c];
        __syncthreads();
        if (r <= KMSG && c < AA) {
            float s = (r == KMSG) ? b_cls[c] : 0.0f;
            #pragma unroll 16
            for (int j = 0; j < HH; j++) s += srow[t >> 6][j] * W_cls[j * AA + c];
            if (r < KMSG) g_W2[r * AA + c] = s;
            else          g_b2[c] = s;
        }
    } else {
        // endpoint occurrence count (self-loop dst deduped)
        int i = (blk - TE_BLOCKS - W2_BLOCKS) * 256 + t;   // < 2*EE
        int e = i >> 1;
        int src = ei[e], dst = ei[EE + e];
        if (!((i & 1) && src == dst))
            atomicAdd(&g_ncount[(i & 1) ? dst : src], 1);
    }
}

// ---------------- P2: compact multi-occurrence endpoints (wide) ------------
__global__ void k_compact(const int* __restrict__ ei) {
    int i = blockIdx.x * blockDim.x + threadIdx.x;
    if (i >= 2 * EE) return;
    int e = i >> 1;
    int src = ei[e], dst = ei[EE + e];
    if ((i & 1) && src == dst) return;             // self-loop dedup
    int v = (i & 1) ? dst : src;
    if (g_ncount[v] >= 2) {
        int pos = atomicAdd(&g_npos, 1);
        g_list[pos] = ((ull)(unsigned)v << 32) | (unsigned)i;
    }
}

// ---------------- P3: bitonic sort -> predecessor extraction ---------------
// One block. Sort (node,pos) keys ascending; equal-node neighbors give pred.
// Deterministic regardless of compaction order (pos is in the key).
__global__ void k_sort_pred() {
    extern __shared__ ull skey[];
    const int t = threadIdx.x, T = blockDim.x;
    const int n = g_npos;
    int m = 2;
    while (m < n) m <<= 1;                          // n <= 16384

    for (int i = t; i < m; i += T)
        skey[i] = (i < n) ? g_list[i] : ~0ull;
    __syncthreads();

    for (int k = 2; k <= m; k <<= 1) {
        for (int j = k >> 1; j > 0; j >>= 1) {
            for (int i = t; i < m; i += T) {
                int ixj = i ^ j;
                if (ixj > i) {
                    ull a = skey[i], b = skey[ixj];
                    bool up = ((i & k) == 0);
                    if ((a > b) == up) { skey[i] = b; skey[ixj] = a; }
                }
            }
            __syncthreads();
        }
    }
    for (int i = t + 1; i < n; i += T) {
        ull a = skey[i - 1], b = skey[i];
        if ((a >> 32) == (b >> 32))
            g_pred[(unsigned)b] = (int)(unsigned)a + 1;   // pos+1 (0 = none)
    }
}

// ---------------- K2: parallel dependency-driven event scan ----------------
// 148 persistent blocks (all co-resident). Block b owns events b, b+148, ...
// Exact sequential semantics via per-endpoint predecessor flags.
// Zero-state invariant: pred == 0 => that node's (h,c) is exactly 0.
// Software pipelining: next owned event's ei/pred/eattr/te are prefetched into
// registers during the current event's compute, hiding their DRAM/L2 latency.
__global__ __launch_bounds__(256, 1)
void k_scan(const int*   __restrict__ ei,
            const float* __restrict__ eattr,
            const float* __restrict__ W_msg,
            const float* __restrict__ b_msg,
            const float* __restrict__ W_ih,
            const float* __restrict__ W_hh,
            const float* __restrict__ b_lstm) {
    __shared__ __align__(16) float s_f0[KMSG];   // feat row0: [hd|hs|ea|te]
    __shared__ __align__(16) float s_f1[KMSG];   // feat row1: [hs|hd|ea|te]
    __shared__ __align__(16) float s_m0[HH];     // relu message row0
    __shared__ __align__(16) float s_m1[HH];     // relu message row1
    __shared__ __align__(16) float s_c[2][HH];   // old cell (cs, cd)
    __shared__ float2 s_part[4][HH];             // message partials {r0, r1}
    __shared__ float2 s_g[4 * HH];               // gates {r0, r1}
    __shared__ float  s_bmsg[HH];
    __shared__ float  s_blstm[4 * HH];

    const int t   = threadIdx.x;
    const int col = t & 63;
    const int seg = t >> 6;
    const int k0  = seg * 48;

    if (t < HH) s_bmsg[t] = b_msg[t];
    s_blstm[t] = b_lstm[t];

    // message weights: this thread holds W_msg[k0..k0+48)[col], k-paired
    ull wm[24];
    #pragma unroll
    for (int j = 0; j < 24; j++)
        wm[j] = f2u(W_msg[(k0 + 2*j) * HH + col], W_msg[(k0 + 2*j + 1) * HH + col]);

    // LSTM weights: full columns t of W_ih and W_hh, k-paired
    ull wih[32], whh[32];
    #pragma unroll
    for (int i = 0; i < 32; i++) {
        wih[i] = f2u(W_ih[(2*i) * 256 + t], W_ih[(2*i + 1) * 256 + t]);
        whh[i] = f2u(W_hh[(2*i) * 256 + t], W_hh[(2*i + 1) * 256 + t]);
    }
    __syncthreads();

    // ---- prefetch event e0 ----
    const int e0 = blockIdx.x;
    int p_src = ei[e0];
    int p_dst = ei[EE + e0];
    int p_ps  = g_pred[2 * e0];
    int p_pd  = g_pred[2 * e0 + 1];
    float p_feat = 0.0f;
    if (t >= 128 && t < 160)      p_feat = eattr[e0 * EA + (t - 128)];
    else if (t >= 160 && t < 192) p_feat = g_te[e0 * TE + (t - 160)];

    for (int e = e0; e < EE; e += GRID_SCAN) {
        const int src  = p_src;
        const int dst  = p_dst;
        const int ps   = p_ps;
        int       pd   = (src == dst) ? p_ps : p_pd;  // self-loop: dst deduped
        const float feat = p_feat;

        // ---- issue prefetch for next owned event (consumed next iter) ----
        {
            int en  = e + GRID_SCAN;
            int eni = (en < EE) ? en : e0;            // safe addr; value unused at tail
            p_src = ei[eni];
            p_dst = ei[EE + eni];
            p_ps  = g_pred[2 * eni];
            p_pd  = g_pred[2 * eni + 1];
            if (t >= 128 && t < 160)      p_feat = eattr[eni * EA + (t - 128)];
            else if (t >= 160 && t < 192) p_feat = g_te[eni * TE + (t - 160)];
        }

        // ---- per-thread wait + state load (zeros when no predecessor) ----
        if (t < 64) {
            float vh = 0.0f, vc = 0.0f;
            if (pd > 0) {
                wait_done((pd - 1) >> 1);
                vh = __ldcg(&g_h[(size_t)dst * HH + t]);
                vc = __ldcg(&g_c[(size_t)dst * HH + t]);
            }
            s_f0[t] = vh;           // row0 leading = hd
            s_f1[64 + t] = vh;      // row1 second  = hd
            s_c[1][t] = vc;
        } else if (t < 128) {
            int i = t - 64;
            float vh = 0.0f, vc = 0.0f;
            if (ps > 0) {
                wait_done((ps - 1) >> 1);
                vh = __ldcg(&g_h[(size_t)src * HH + i]);
                vc = __ldcg(&g_c[(size_t)src * HH + i]);
            }
            s_f0[64 + i] = vh;      // row0 second  = hs
            s_f1[i] = vh;           // row1 leading = hs
            s_c[0][i] = vc;
        } else if (t < 192) {
            s_f0[t] = feat;         // ea at [128,160), te at [160,192)
            s_f1[t] = feat;
        }
        __syncthreads();

        // ---- message GEMM: [2,192] @ [192,64] (4 k-segment partials) ----
        {
            ull a0 = 0ull, a1 = 0ull;
            #pragma unroll
            for (int j = 0; j < 24; j++) {
                ull f0 = *(const ull*)(s_f0 + k0 + 2*j);
                ull f1 = *(const ull*)(s_f1 + k0 + 2*j);
                a0 = ffma2(f0, wm[j], a0);
                a1 = ffma2(f1, wm[j], a1);
            }
            float2 p0 = u2f(a0), p1 = u2f(a1);
            s_part[seg][col] = make_float2(p0.x + p0.y, p1.x + p1.y);
        }
        __syncthreads();

        if (t < HH) {
            float2 s = s_part[0][t];
            #pragma unroll
            for (int q = 1; q < 4; q++) { s.x += s_part[q][t].x; s.y += s_part[q][t].y; }
            float b = s_bmsg[t];
            s_m0[t] = fmaxf(s.x + b, 0.0f);
            s_m1[t] = fmaxf(s.y + b, 0.0f);
        }
        __syncthreads();

        // ---- LSTM gates: g = m@W_ih + h_old@W_hh + b (split accumulators) --
        {
            ull a0 = 0ull, b0 = 0ull, a1 = 0ull, b1 = 0ull;
            #pragma unroll
            for (int i = 0; i < 32; i++) {
                a0 = ffma2(*(const ull*)(s_m0 + 2*i),      wih[i], a0);
                a1 = ffma2(*(const ull*)(s_m1 + 2*i),      wih[i], a1);
                b0 = ffma2(*(const ull*)(s_f0 + 64 + 2*i), whh[i], b0);  // hs (row0)
                b1 = ffma2(*(const ull*)(s_f1 + 64 + 2*i), whh[i], b1);  // hd (row1)
            }
            float2 g0 = u2f(a0), h0 = u2f(b0), g1 = u2f(a1), h1 = u2f(b1);
            float b = s_blstm[t];
            s_g[t] = make_float2(g0.x + g0.y + h0.x + h0.y + b,
                                 g1.x + g1.y + h1.x + h1.y + b);
        }
        __syncthreads();

        // ---- elementwise LSTM + writeback ----
        if (t < 128) {
            int r = t >> 6, cc = t & 63;
            float2 vi = s_g[cc], vf = s_g[64 + cc], vg = s_g[128 + cc], vo = s_g[192 + cc];
            float gi = r ? vi.y : vi.x;
            float gf = r ? vf.y : vf.x;
            float gg = r ? vg.y : vg.x;
            float go = r ? vo.y : vo.x;
            float co = s_c[r][cc];
            float cn = sigm(gf) * co + sigm(gi) * tanh_s(gg);
            float hn = sigm(go) * tanh_s(cn);
            int node = r ? dst : src;
            // duplicate-index semantics: dst (row 1) wins, matching scatter order
            if (!(r == 0 && src == dst)) {
                __stcg(&g_h[(size_t)node * HH + cc], hn);
                __stcg(&g_c[(size_t)node * HH + cc], cn);
            }
        }
        __syncthreads();                 // writes done block-wide before release

        if (t == 0) signal_done(e);      // release: publishes h/c to consumers
    }
}

// ---------------- K3: logits + scratch cleanup -----------------------------
// 256 blocks x 256 threads; W2+b2 staged in smem once per block; each warp
// handles 4 edges with broadcast float4 z reads and conflict-free sW2 reads.
#define LOG_BLOCKS 256
__global__ __launch_bounds__(256)
void k_logits(const int* __restrict__ ei,
              const float* __restrict__ x,
              float* __restrict__ out) {
    __shared__ __align__(16) float sW2[KMSG * AA];  // 38.4 KB
    __shared__ float sb2[AA];
    __shared__ __align__(16) float zbuf[8][KMSG];   // per-warp z staging

    const int t    = threadIdx.x;
    const int warp = t >> 5;
    const int lane = t & 31;

    for (int i = t; i < KMSG * AA; i += 256) sW2[i] = g_W2[i];
    if (t < AA) sb2[t] = g_b2[t];
    if (blockIdx.x == 0 && t == 0) g_npos = 0;      // restore call-entry invariant
    __syncthreads();

    #pragma unroll
    for (int it = 0; it < 4; it++) {
        int e = blockIdx.x * 8 + warp + it * (LOG_BLOCKS * 8);
        int src = ei[e];
        int dst = ei[EE + e];

        // cleanup for next replay (benign 0-write races)
        if (lane == 0) {
            g_done[e] = 0;
            g_pred[2 * e] = 0;
            g_pred[2 * e + 1] = 0;
            g_ncount[src] = 0;
            g_ncount[dst] = 0;
        }

        // gather z: h[dst] (64) then x[dst] (128); 6 floats per lane
        {
            const float* hp = &g_h[(size_t)dst * HH];
            const float* xp = &x[(size_t)dst * DFEAT];
            zbuf[warp][lane]       = hp[lane];
            zbuf[warp][lane + 32]  = hp[lane + 32];
            zbuf[warp][lane + 64]  = xp[lane];
            zbuf[warp][lane + 96]  = xp[lane + 32];
            zbuf[warp][lane + 128] = xp[lane + 64];
            zbuf[warp][lane + 160] = xp[lane + 96];
        }
        __syncwarp();

        // pass 0: cols 0..31   pass 1: cols 32..49
        #pragma unroll
        for (int p = 0; p < 2; p++) {
            int c = p * 32 + lane;
            if (c < AA) {
                float acc = sb2[c];
                #pragma unroll 8
                for (int i = 0; i < KMSG; i += 4) {
                    float4 z4 = *(const float4*)(&zbuf[warp][i]);   // broadcast
                    acc += z4.x * sW2[(i    ) * AA + c];
                    acc += z4.y * sW2[(i + 1) * AA + c];
                    acc += z4.z * sW2[(i + 2) * AA + c];
                    acc += z4.w * sW2[(i + 3) * AA + c];
                }
                out[e * AA + c] = acc;
            }
        }
        __syncwarp();
    }
}

// ---------------- launch ----------------
extern "C" void kernel_launch(void* const* d_in, const int* in_sizes, int n_in,
                              void* d_out, int out_size) {
    const float* x      = (const float*)d_in[0];
    const int*   ei     = (const int*)  d_in[1];
    const float* eattr  = (const float*)d_in[2];
    const float* etime  = (const float*)d_in[3];
    const float* tw     = (const float*)d_in[4];
    const float* tb     = (const float*)d_in[5];
    const float* Wmsg   = (const float*)d_in[6];
    const float* bmsg   = (const float*)d_in[7];
    const float* Wih    = (const float*)d_in[8];
    const float* Whh    = (const float*)d_in[9];
    const float* blstm  = (const float*)d_in[10];
    const float* Wemb   = (const float*)d_in[11];
    const float* bemb   = (const float*)d_in[12];
    const float* Wcls   = (const float*)d_in[13];
    const float* bcls   = (const float*)d_in[14];
    float* out = (float*)d_out;

    // idempotent, host-side only (not a stream op) -> safe under capture
    cudaFuncSetAttribute(k_sort_pred,
                         cudaFuncAttributeMaxDynamicSharedMemorySize,
                         2 * EE * (int)sizeof(unsigned long long));

    k_pre      <<<TE_BLOCKS + W2_BLOCKS + CNT_BLOCKS, 256>>>(
                   etime, tw, tb, Wemb, bemb, Wcls, bcls, ei);
    k_compact  <<<(2 * EE + 255) / 256, 256>>>(ei);
    k_sort_pred<<<1, 1024, 2 * EE * (int)sizeof(unsigned long long)>>>();
    k_scan     <<<GRID_SCAN, 256>>>(ei, eattr, Wmsg, bmsg, Wih, Whh, blstm);
    k_logits   <<<LOG_BLOCKS, 256>>>(ei, x, out);
}